// round 1
// baseline (speedup 1.0000x reference)
#include <cuda_runtime.h>
#include <cuda_bf16.h>
#include <cstdint>

// Problem shape (fixed by the dataset)
#define B_  32
#define T_  768
#define C_  448
#define E_  256
#define N_  3136          // H*W = 56*56
#define SCALE 0.0625f     // 1/sqrt(E)

#define CHUNK 16
#define NCHUNK (N_ / CHUNK)   // 196
#define PITCH 17              // smem row pitch (odd -> conflict-light)

// -------- device scratch (no allocations allowed) --------
__device__ float g_a[B_ * C_];                 // scale * (q[b]^T k_w)[c]
__device__ float g_qkb[B_];                    // scale * q[b].k_b
__device__ float g_Spart[B_ * NCHUNK * C_];    // per-chunk weighted channel sums
__device__ float g_Dpart[B_ * NCHUNK];         // per-chunk exp-sum partials
__device__ float g_out[B_ * C_];               // final per-(b,c) residual add

// ============================================================
// Kernel 1: q = text @ q_w^T + q_b;  a[b,c] = scale * q.k_w[:,c];
//           qkb[b] = scale * q.k_b.   One block per batch.
// ============================================================
__global__ void __launch_bounds__(256) k_compute_qa(
    const float* __restrict__ text, const float* __restrict__ q_w,
    const float* __restrict__ q_b, const float* __restrict__ k_w,
    const float* __restrict__ k_b)
{
    int b = blockIdx.x, tid = threadIdx.x;
    __shared__ float txt[T_];
    __shared__ float q_sm[E_];
    __shared__ float red[E_];

    for (int t = tid; t < T_; t += 256) txt[t] = text[b * T_ + t];
    __syncthreads();

    // each thread computes one q element (E_ == 256 == blockDim)
    {
        float acc = q_b[tid];
        const float* w = q_w + (size_t)tid * T_;
        #pragma unroll 8
        for (int t = 0; t < T_; ++t) acc += txt[t] * w[t];
        q_sm[tid] = acc;
        red[tid] = acc * k_b[tid];
    }
    __syncthreads();
    // block reduce for qkb
    for (int s = 128; s > 0; s >>= 1) {
        if (tid < s) red[tid] += red[tid + s];
        __syncthreads();
    }
    if (tid == 0) g_qkb[b] = SCALE * red[0];

    // a[b,c] = scale * sum_e q[e] * k_w[e*C + c]   (coalesced over c)
    for (int c = tid; c < C_; c += 256) {
        float acc = 0.f;
        #pragma unroll 8
        for (int e = 0; e < E_; ++e) acc += q_sm[e] * k_w[e * C_ + c];
        g_a[b * C_ + c] = SCALE * acc;
    }
}

// ============================================================
// Kernel 2: one image pass. Block = (chunk, b). Stages a
// [C_ x CHUNK] tile in smem, computes exp(logits) for its 16
// pixels, then the attention-weighted partial channel sums.
// ============================================================
__global__ void __launch_bounds__(256) k_attn_pass(const float* __restrict__ img)
{
    int chunk = blockIdx.x, b = blockIdx.y;
    int tid = threadIdx.x;
    int n0 = chunk * CHUNK;

    __shared__ float tile[C_ * PITCH];   // 448*17*4 = 30464 B
    __shared__ float a_sm[C_];
    __shared__ float red[256];
    __shared__ float e_sm[CHUNK];

    for (int c = tid; c < C_; c += 256) a_sm[c] = g_a[b * C_ + c];

    // load tile: 448 rows x 4 float4 each
    const float* base = img + (size_t)b * C_ * N_ + n0;
    for (int idx = tid; idx < C_ * 4; idx += 256) {
        int c = idx >> 2, v = idx & 3;
        float4 x = *reinterpret_cast<const float4*>(base + (size_t)c * N_ + v * 4);
        float* t = tile + c * PITCH + v * 4;
        t[0] = x.x; t[1] = x.y; t[2] = x.z; t[3] = x.w;
    }
    __syncthreads();

    // Phase A: logits. 16 groups x 16 pixels; each group covers 28 channels.
    int n = tid & 15, g = tid >> 4;     // g in [0,16)
    {
        float p = 0.f;
        int c0 = g * 28;
        #pragma unroll
        for (int c = c0; c < c0 + 28; ++c) p += a_sm[c] * tile[c * PITCH + n];
        red[g * 16 + n] = p;
    }
    __syncthreads();

    if (tid < 16) {
        float l = 0.f;
        #pragma unroll
        for (int gg = 0; gg < 16; ++gg) l += red[gg * 16 + tid];
        float e = __expf(l + g_qkb[b]);
        e_sm[tid] = e;
        float d = e;
        d += __shfl_xor_sync(0xffffu, d, 8);
        d += __shfl_xor_sync(0xffffu, d, 4);
        d += __shfl_xor_sync(0xffffu, d, 2);
        d += __shfl_xor_sync(0xffffu, d, 1);
        if (tid == 0) g_Dpart[b * NCHUNK + chunk] = d;
    }
    __syncthreads();

    // Phase B: partial numerators S[c] = sum_n e[n] * x[c,n]
    float* Sp = g_Spart + ((size_t)(b * NCHUNK + chunk)) * C_;
    for (int c = tid; c < C_; c += 256) {
        float acc = 0.f;
        const float* t = tile + c * PITCH;
        #pragma unroll
        for (int j = 0; j < CHUNK; ++j) acc += e_sm[j] * t[j];
        Sp[c] = acc;
    }
}

// ============================================================
// Kernel 3: reduce partials, pooled = v_w @ (s/D) + v_b,
//           out[b,c] = o_w @ pooled + o_b.  One block per batch.
// ============================================================
__global__ void __launch_bounds__(256) k_finish(
    const float* __restrict__ v_w, const float* __restrict__ v_b,
    const float* __restrict__ o_w, const float* __restrict__ o_b)
{
    int b = blockIdx.x, tid = threadIdx.x;
    __shared__ float s_sm[C_];
    __shared__ float pooled[E_];
    __shared__ float invD_sm;

    for (int c = tid; c < C_; c += 256) {
        float acc = 0.f;
        const float* Sp = g_Spart + (size_t)b * NCHUNK * C_ + c;
        #pragma unroll 4
        for (int ch = 0; ch < NCHUNK; ++ch) acc += Sp[(size_t)ch * C_];
        s_sm[c] = acc;
    }
    if (tid < 32) {
        float d = 0.f;
        for (int ch = tid; ch < NCHUNK; ch += 32) d += g_Dpart[b * NCHUNK + ch];
        #pragma unroll
        for (int o = 16; o > 0; o >>= 1) d += __shfl_xor_sync(0xffffffffu, d, o);
        if (tid == 0) invD_sm = 1.0f / d;
    }
    __syncthreads();
    float invD = invD_sm;

    // pooled[e] (E_ == 256 == blockDim)
    {
        float acc = 0.f;
        const float* w = v_w + (size_t)tid * C_;
        #pragma unroll 8
        for (int c = 0; c < C_; ++c) acc += w[c] * s_sm[c];
        pooled[tid] = acc * invD + v_b[tid];
    }
    __syncthreads();

    for (int c = tid; c < C_; c += 256) {
        float acc = o_b[c];
        const float* w = o_w + (size_t)c * E_;
        #pragma unroll 8
        for (int e = 0; e < E_; ++e) acc += w[e] * pooled[e];
        g_out[b * C_ + c] = acc;
    }
}

// ============================================================
// Kernel 4: out_img = img + out[b,c]  (float4 streaming)
// ============================================================
__global__ void __launch_bounds__(256) k_residual(const float* __restrict__ img,
                                                  float* __restrict__ out)
{
    int idx = blockIdx.x * 256 + threadIdx.x;       // float4 index
    // total float4s = B*C*N/4 = 11,239,424 = 43904 * 256, exact
    int bc = idx / (N_ / 4);                        // N_/4 = 784
    float add = __ldg(&g_out[bc]);
    float4 x = reinterpret_cast<const float4*>(img)[idx];
    x.x += add; x.y += add; x.z += add; x.w += add;
    reinterpret_cast<float4*>(out)[idx] = x;
}

// ============================================================
extern "C" void kernel_launch(void* const* d_in, const int* in_sizes, int n_in,
                              void* d_out, int out_size)
{
    const float* text = (const float*)d_in[0];
    const float* img  = (const float*)d_in[1];
    const float* q_w  = (const float*)d_in[2];
    const float* q_b  = (const float*)d_in[3];
    const float* k_w  = (const float*)d_in[4];
    const float* k_b  = (const float*)d_in[5];
    const float* v_w  = (const float*)d_in[6];
    const float* v_b  = (const float*)d_in[7];
    const float* o_w  = (const float*)d_in[8];
    const float* o_b  = (const float*)d_in[9];
    float* out = (float*)d_out;

    k_compute_qa<<<B_, 256>>>(text, q_w, q_b, k_w, k_b);
    k_attn_pass<<<dim3(NCHUNK, B_), 256>>>(img);
    k_finish<<<B_, 256>>>(v_w, v_b, o_w, o_b);
    k_residual<<<(B_ * C_ * (N_ / 4)) / 256, 256>>>(img, out);
}

// round 2
// speedup vs baseline: 1.6302x; 1.6302x over previous
#include <cuda_runtime.h>
#include <cuda_bf16.h>
#include <cstdint>

// Problem shape (fixed by the dataset)
#define B_  32
#define T_  768
#define C_  448
#define E_  256
#define N_  3136          // H*W = 56*56
#define SCALE 0.0625f     // 1/sqrt(E)

#define CHUNK 16
#define NCHUNK (N_ / CHUNK)   // 196
#define PITCH 17              // smem row pitch (odd -> conflict-light)

// -------- device scratch (no allocations allowed) --------
__device__ float g_a[B_ * C_];                 // scale * (q[b]^T k_w)[c]
__device__ float g_qkb[B_];                    // scale * q[b].k_b
__device__ float g_Spart[B_ * NCHUNK * C_];    // per-chunk weighted channel sums
__device__ float g_Dpart[B_ * NCHUNK];         // per-chunk exp-sum partials
__device__ float g_out[B_ * C_];               // final per-(b,c) residual add

// ============================================================
// Kernel 1: q = text @ q_w^T + q_b;  a[b,c] = scale * q.k_w[:,c];
//           qkb[b] = scale * q.k_b.   One block per batch.
// Warp-per-output with lane-coalesced row reads (no 32-line LDGs).
// ============================================================
__global__ void __launch_bounds__(256) k_compute_qa(
    const float* __restrict__ text, const float* __restrict__ q_w,
    const float* __restrict__ q_b, const float* __restrict__ k_w,
    const float* __restrict__ k_b)
{
    int b = blockIdx.x, tid = threadIdx.x;
    int warp = tid >> 5, lane = tid & 31;
    __shared__ float txt[T_];
    __shared__ float q_sm[E_];
    __shared__ float red[256];

    const float4* tsrc = reinterpret_cast<const float4*>(text + (size_t)b * T_);
    for (int j = tid; j < T_ / 4; j += 256)
        reinterpret_cast<float4*>(txt)[j] = tsrc[j];
    __syncthreads();

    // q[e]: warp computes 32 outputs, lanes read q_w row coalesced (float4)
    for (int r = 0; r < 32; ++r) {
        int e = warp * 32 + r;
        const float4* w = reinterpret_cast<const float4*>(q_w + (size_t)e * T_);
        const float4* tt = reinterpret_cast<const float4*>(txt);
        float acc = 0.f;
        #pragma unroll
        for (int it = 0; it < 6; ++it) {         // 6*32*4 = 768 exact
            int j = it * 32 + lane;
            float4 x = w[j], y = tt[j];
            acc += x.x * y.x + x.y * y.y + x.z * y.z + x.w * y.w;
        }
        #pragma unroll
        for (int o = 16; o > 0; o >>= 1) acc += __shfl_down_sync(0xffffffffu, acc, o);
        if (lane == 0) q_sm[e] = acc + q_b[e];
    }
    __syncthreads();

    red[tid] = q_sm[tid] * k_b[tid];
    __syncthreads();
    for (int s = 128; s > 0; s >>= 1) {
        if (tid < s) red[tid] += red[tid + s];
        __syncthreads();
    }
    if (tid == 0) g_qkb[b] = SCALE * red[0];

    // a[b,c] = scale * sum_e q[e] * k_w[e*C + c]   (lanes -> consecutive c, coalesced)
    for (int c = tid; c < C_; c += 256) {
        float acc = 0.f;
        #pragma unroll 8
        for (int e = 0; e < E_; ++e) acc += q_sm[e] * k_w[e * C_ + c];
        g_a[b * C_ + c] = SCALE * acc;
    }
}

// ============================================================
// Kernel 2: one image pass. Block = (chunk, b). Stages a
// [C_ x CHUNK] tile in smem, computes exp(logits) for its 16
// pixels, then the attention-weighted partial channel sums.
// ============================================================
__global__ void __launch_bounds__(256) k_attn_pass(const float* __restrict__ img)
{
    int chunk = blockIdx.x, b = blockIdx.y;
    int tid = threadIdx.x;
    int n0 = chunk * CHUNK;

    __shared__ float tile[C_ * PITCH];   // 448*17*4 = 30464 B
    __shared__ float a_sm[C_];
    __shared__ float red[256];
    __shared__ float e_sm[CHUNK];

    for (int c = tid; c < C_; c += 256) a_sm[c] = g_a[b * C_ + c];

    // load tile: 448 rows x 4 float4 each
    const float* base = img + (size_t)b * C_ * N_ + n0;
    for (int idx = tid; idx < C_ * 4; idx += 256) {
        int c = idx >> 2, v = idx & 3;
        float4 x = *reinterpret_cast<const float4*>(base + (size_t)c * N_ + v * 4);
        float* t = tile + c * PITCH + v * 4;
        t[0] = x.x; t[1] = x.y; t[2] = x.z; t[3] = x.w;
    }
    __syncthreads();

    // Phase A: logits. 16 groups x 16 pixels; each group covers 28 channels.
    int n = tid & 15, g = tid >> 4;     // g in [0,16)
    {
        float p = 0.f;
        int c0 = g * 28;
        #pragma unroll
        for (int c = c0; c < c0 + 28; ++c) p += a_sm[c] * tile[c * PITCH + n];
        red[g * 16 + n] = p;
    }
    __syncthreads();

    if (tid < 16) {
        float l = 0.f;
        #pragma unroll
        for (int gg = 0; gg < 16; ++gg) l += red[gg * 16 + tid];
        float e = __expf(l + g_qkb[b]);
        e_sm[tid] = e;
        float d = e;
        d += __shfl_xor_sync(0xffffu, d, 8);
        d += __shfl_xor_sync(0xffffu, d, 4);
        d += __shfl_xor_sync(0xffffu, d, 2);
        d += __shfl_xor_sync(0xffffu, d, 1);
        if (tid == 0) g_Dpart[b * NCHUNK + chunk] = d;
    }
    __syncthreads();

    // Phase B: partial numerators S[c] = sum_n e[n] * x[c,n]
    float* Sp = g_Spart + ((size_t)(b * NCHUNK + chunk)) * C_;
    for (int c = tid; c < C_; c += 256) {
        float acc = 0.f;
        const float* t = tile + c * PITCH;
        #pragma unroll
        for (int j = 0; j < CHUNK; ++j) acc += e_sm[j] * t[j];
        Sp[c] = acc;
    }
}

// ============================================================
// Kernel 3: reduce partials, pooled = v_w @ (s/D) + v_b,
//           out[b,c] = o_w @ pooled + o_b.  One block per batch.
// Warp-per-output, lane-coalesced weight reads.
// ============================================================
__global__ void __launch_bounds__(256) k_finish(
    const float* __restrict__ v_w, const float* __restrict__ v_b,
    const float* __restrict__ o_w, const float* __restrict__ o_b)
{
    int b = blockIdx.x, tid = threadIdx.x;
    int warp = tid >> 5, lane = tid & 31;
    __shared__ float s_sm[C_];
    __shared__ float pooled[E_];
    __shared__ float invD_sm;

    // reduce Spart: lanes -> consecutive c (coalesced), deep ILP over chunks
    for (int c = tid; c < C_; c += 256) {
        const float* Sp = g_Spart + (size_t)b * NCHUNK * C_ + c;
        float a0 = 0.f, a1 = 0.f, a2 = 0.f, a3 = 0.f;
        #pragma unroll 4
        for (int ch = 0; ch < NCHUNK; ch += 4) {      // 196 = 49*4 exact
            a0 += Sp[(size_t)(ch + 0) * C_];
            a1 += Sp[(size_t)(ch + 1) * C_];
            a2 += Sp[(size_t)(ch + 2) * C_];
            a3 += Sp[(size_t)(ch + 3) * C_];
        }
        s_sm[c] = (a0 + a1) + (a2 + a3);
    }
    if (tid < 32) {
        float d = 0.f;
        for (int ch = tid; ch < NCHUNK; ch += 32) d += g_Dpart[b * NCHUNK + ch];
        #pragma unroll
        for (int o = 16; o > 0; o >>= 1) d += __shfl_xor_sync(0xffffffffu, d, o);
        if (tid == 0) invD_sm = 1.0f / d;
    }
    __syncthreads();
    float invD = invD_sm;

    // pooled[e]: warp per output, lanes coalesced over c (448 = 14*32)
    for (int r = 0; r < 32; ++r) {
        int e = warp * 32 + r;
        const float* w = v_w + (size_t)e * C_;
        float acc = 0.f;
        #pragma unroll
        for (int it = 0; it < 14; ++it) {
            int c = it * 32 + lane;
            acc += w[c] * s_sm[c];
        }
        #pragma unroll
        for (int o = 16; o > 0; o >>= 1) acc += __shfl_down_sync(0xffffffffu, acc, o);
        if (lane == 0) pooled[e] = acc * invD + v_b[e];
    }
    __syncthreads();

    // out[b,c]: warp per output c (448 = 8*56), lanes coalesced over e (256 = 8*32)
    for (int r = 0; r < 56; ++r) {
        int c = warp * 56 + r;
        const float* w = o_w + (size_t)c * E_;
        float acc = 0.f;
        #pragma unroll
        for (int it = 0; it < 8; ++it) {
            int e = it * 32 + lane;
            acc += w[e] * pooled[e];
        }
        #pragma unroll
        for (int o = 16; o > 0; o >>= 1) acc += __shfl_down_sync(0xffffffffu, acc, o);
        if (lane == 0) g_out[b * C_ + c] = acc + o_b[c];
    }
}

// ============================================================
// Kernel 4: out_img = img + out[b,c]  (float4 streaming)
// ============================================================
__global__ void __launch_bounds__(256) k_residual(const float* __restrict__ img,
                                                  float* __restrict__ out)
{
    int idx = blockIdx.x * 256 + threadIdx.x;       // float4 index
    // total float4s = B*C*N/4 = 11,239,424 = 43904 * 256, exact
    int bc = idx / (N_ / 4);                        // N_/4 = 784
    float add = __ldg(&g_out[bc]);
    float4 x = reinterpret_cast<const float4*>(img)[idx];
    x.x += add; x.y += add; x.z += add; x.w += add;
    reinterpret_cast<float4*>(out)[idx] = x;
}

// ============================================================
extern "C" void kernel_launch(void* const* d_in, const int* in_sizes, int n_in,
                              void* d_out, int out_size)
{
    const float* text = (const float*)d_in[0];
    const float* img  = (const float*)d_in[1];
    const float* q_w  = (const float*)d_in[2];
    const float* q_b  = (const float*)d_in[3];
    const float* k_w  = (const float*)d_in[4];
    const float* k_b  = (const float*)d_in[5];
    const float* v_w  = (const float*)d_in[6];
    const float* v_b  = (const float*)d_in[7];
    const float* o_w  = (const float*)d_in[8];
    const float* o_b  = (const float*)d_in[9];
    float* out = (float*)d_out;

    k_compute_qa<<<B_, 256>>>(text, q_w, q_b, k_w, k_b);
    k_attn_pass<<<dim3(NCHUNK, B_), 256>>>(img);
    k_finish<<<B_, 256>>>(v_w, v_b, o_w, o_b);
    k_residual<<<(B_ * C_ * (N_ / 4)) / 256, 256>>>(img, out);
}

// round 3
// speedup vs baseline: 1.8901x; 1.1595x over previous
#include <cuda_runtime.h>
#include <cuda_bf16.h>
#include <cstdint>

// Problem shape (fixed by the dataset)
#define B_  32
#define T_  768
#define C_  448
#define E_  256
#define N_  3136          // H*W = 56*56
#define SCALE 0.0625f     // 1/sqrt(E)

#define CHUNK 16
#define PITCH 17              // smem row pitch (odd -> conflict-free)
#define GX 28                 // pixel-groups per batch (blocks in x)
#define CPB 7                 // chunks per block: 28*7*16 = 3136 exact

// -------- device scratch (no allocations allowed) --------
__device__ float g_a[B_ * C_];              // scale * (q[b]^T k_w)[c]
__device__ float g_qkb[B_];                 // scale * q[b].k_b
__device__ float g_Spart[B_ * GX * C_];     // per-group weighted channel sums
__device__ float g_Dpart[B_ * GX];          // per-group exp-sum partials
__device__ float g_out[B_ * C_];            // final per-(b,c) residual add

// ============================================================
// Kernel 1: q = text @ q_w^T + q_b;  a[b,c] = scale * q.k_w[:,c];
//           qkb[b] = scale * q.k_b.   One block per batch.
// ============================================================
__global__ void __launch_bounds__(256) k_compute_qa(
    const float* __restrict__ text, const float* __restrict__ q_w,
    const float* __restrict__ q_b, const float* __restrict__ k_w,
    const float* __restrict__ k_b)
{
    int b = blockIdx.x, tid = threadIdx.x;
    int warp = tid >> 5, lane = tid & 31;
    __shared__ float txt[T_];
    __shared__ float q_sm[E_];
    __shared__ float red[256];

    const float4* tsrc = reinterpret_cast<const float4*>(text + (size_t)b * T_);
    for (int j = tid; j < T_ / 4; j += 256)
        reinterpret_cast<float4*>(txt)[j] = tsrc[j];
    __syncthreads();

    // q[e]: warp computes 32 outputs (2 at a time for load/shuffle overlap)
    for (int r = 0; r < 32; r += 2) {
        int e0 = warp * 32 + r, e1 = e0 + 1;
        const float4* w0 = reinterpret_cast<const float4*>(q_w + (size_t)e0 * T_);
        const float4* w1 = reinterpret_cast<const float4*>(q_w + (size_t)e1 * T_);
        const float4* tt = reinterpret_cast<const float4*>(txt);
        float a0 = 0.f, a1 = 0.f;
        #pragma unroll
        for (int it = 0; it < 6; ++it) {         // 6*32*4 = 768 exact
            int j = it * 32 + lane;
            float4 y = tt[j];
            float4 x0 = w0[j], x1 = w1[j];
            a0 += x0.x * y.x + x0.y * y.y + x0.z * y.z + x0.w * y.w;
            a1 += x1.x * y.x + x1.y * y.y + x1.z * y.z + x1.w * y.w;
        }
        #pragma unroll
        for (int o = 16; o > 0; o >>= 1) {
            a0 += __shfl_down_sync(0xffffffffu, a0, o);
            a1 += __shfl_down_sync(0xffffffffu, a1, o);
        }
        if (lane == 0) { q_sm[e0] = a0 + q_b[e0]; q_sm[e1] = a1 + q_b[e1]; }
    }
    __syncthreads();

    red[tid] = q_sm[tid] * k_b[tid];
    __syncthreads();
    for (int s = 128; s > 0; s >>= 1) {
        if (tid < s) red[tid] += red[tid + s];
        __syncthreads();
    }
    if (tid == 0) g_qkb[b] = SCALE * red[0];

    // a[b,c] = scale * sum_e q[e] * k_w[e*C + c]   (lanes -> consecutive c)
    for (int c = tid; c < C_; c += 256) {
        float acc = 0.f;
        #pragma unroll 8
        for (int e = 0; e < E_; ++e) acc += q_sm[e] * k_w[e * C_ + c];
        g_a[b * C_ + c] = SCALE * acc;
    }
}

// ============================================================
// Kernel 2: attention pass. Block (gx, b) processes CPB chunks
// of 16 pixels. a_sm loaded once; S accumulated in registers.
// ============================================================
__global__ void __launch_bounds__(256) k_attn_pass(const float* __restrict__ img)
{
    int gx = blockIdx.x, b = blockIdx.y;
    int tid = threadIdx.x;
    int warp = tid >> 5, lane = tid & 31;

    __shared__ float tile[C_ * PITCH];   // 448*17*4 = 30464 B
    __shared__ float a_sm[C_];
    __shared__ float e_sm[CHUNK];
    __shared__ float d_sm[8];

    for (int c = tid; c < C_; c += 256) a_sm[c] = g_a[b * C_ + c];
    float qkb = g_qkb[b];

    const float* base = img + (size_t)b * C_ * N_ + gx * (CPB * CHUNK);

    float sAcc0 = 0.f, sAcc1 = 0.f;   // channels tid and tid+256
    float dAcc = 0.f;                  // per-warp (lane0) exp-sum

    for (int i = 0; i < CPB; ++i) {
        // ---- load tile: 448 rows x 4 float4 each ----
        const float* src = base + i * CHUNK;
        #pragma unroll
        for (int it = 0; it < 7; ++it) {
            int idx = it * 256 + tid;          // < 1792
            int c = idx >> 2, v = idx & 3;
            float4 x = *reinterpret_cast<const float4*>(src + (size_t)c * N_ + v * 4);
            float* t = tile + c * PITCH + v * 4;
            t[0] = x.x; t[1] = x.y; t[2] = x.z; t[3] = x.w;
        }
        __syncthreads();

        // ---- Phase A: logits. warp w owns pixels 2w, 2w+1 ----
        {
            float p0 = 0.f, p1 = 0.f;
            int px = warp * 2;
            #pragma unroll
            for (int j = 0; j < 14; ++j) {
                int c = j * 32 + lane;
                float av = a_sm[c];
                const float* t = tile + c * PITCH + px;
                p0 += av * t[0];
                p1 += av * t[1];
            }
            #pragma unroll
            for (int o = 16; o > 0; o >>= 1) {
                p0 += __shfl_xor_sync(0xffffffffu, p0, o);
                p1 += __shfl_xor_sync(0xffffffffu, p1, o);
            }
            if (lane == 0) {
                float e0 = __expf(p0 + qkb);
                float e1 = __expf(p1 + qkb);
                e_sm[px] = e0; e_sm[px + 1] = e1;
                dAcc += e0 + e1;
            }
        }
        __syncthreads();

        // ---- Phase B: S[c] += sum_j e[j] * x[c,j] ----
        {
            const float* t0 = tile + tid * PITCH;
            float a0 = 0.f, a1 = 0.f;
            if (tid < 192) {
                const float* t1 = tile + (tid + 256) * PITCH;
                #pragma unroll
                for (int j = 0; j < CHUNK; ++j) {
                    float e = e_sm[j];
                    a0 += e * t0[j];
                    a1 += e * t1[j];
                }
            } else {
                #pragma unroll
                for (int j = 0; j < CHUNK; ++j) a0 += e_sm[j] * t0[j];
            }
            sAcc0 += a0; sAcc1 += a1;
        }
        __syncthreads();
    }

    // ---- write partials ----
    float* Sp = g_Spart + ((size_t)(b * GX + gx)) * C_;
    Sp[tid] = sAcc0;
    if (tid < 192) Sp[tid + 256] = sAcc1;

    if (lane == 0) d_sm[warp] = dAcc;
    __syncthreads();
    if (tid == 0) {
        float d = 0.f;
        #pragma unroll
        for (int w = 0; w < 8; ++w) d += d_sm[w];
        g_Dpart[b * GX + gx] = d;
    }
}

// ============================================================
// Kernel 3: reduce partials, pooled = v_w @ (s/D) + v_b,
//           out[b,c] = o_w @ pooled + o_b.  One block per batch.
// ============================================================
__global__ void __launch_bounds__(256) k_finish(
    const float* __restrict__ v_w, const float* __restrict__ v_b,
    const float* __restrict__ o_w, const float* __restrict__ o_b)
{
    int b = blockIdx.x, tid = threadIdx.x;
    int warp = tid >> 5, lane = tid & 31;
    __shared__ float s_sm[C_];
    __shared__ float pooled[E_];
    __shared__ float invD_sm;

    for (int c = tid; c < C_; c += 256) {
        const float* Sp = g_Spart + (size_t)b * GX * C_ + c;
        float a0 = 0.f, a1 = 0.f;
        #pragma unroll
        for (int g = 0; g < GX; g += 2) {
            a0 += Sp[(size_t)(g + 0) * C_];
            a1 += Sp[(size_t)(g + 1) * C_];
        }
        s_sm[c] = a0 + a1;
    }
    if (tid < 32) {
        float d = (tid < GX) ? g_Dpart[b * GX + tid] : 0.f;
        #pragma unroll
        for (int o = 16; o > 0; o >>= 1) d += __shfl_xor_sync(0xffffffffu, d, o);
        if (tid == 0) invD_sm = 1.0f / d;
    }
    __syncthreads();
    float invD = invD_sm;

    // pooled[e]: warp per output, lanes coalesced over c (448 = 14*32)
    for (int r = 0; r < 32; ++r) {
        int e = warp * 32 + r;
        const float* w = v_w + (size_t)e * C_;
        float acc = 0.f;
        #pragma unroll
        for (int it = 0; it < 14; ++it) {
            int c = it * 32 + lane;
            acc += w[c] * s_sm[c];
        }
        #pragma unroll
        for (int o = 16; o > 0; o >>= 1) acc += __shfl_down_sync(0xffffffffu, acc, o);
        if (lane == 0) pooled[e] = acc * invD + v_b[e];
    }
    __syncthreads();

    // out[b,c]: warp per output c (448 = 8*56), lanes coalesced over e
    for (int r = 0; r < 56; ++r) {
        int c = warp * 56 + r;
        const float* w = o_w + (size_t)c * E_;
        float acc = 0.f;
        #pragma unroll
        for (int it = 0; it < 8; ++it) {
            int e = it * 32 + lane;
            acc += w[e] * pooled[e];
        }
        #pragma unroll
        for (int o = 16; o > 0; o >>= 1) acc += __shfl_down_sync(0xffffffffu, acc, o);
        if (lane == 0) g_out[b * C_ + c] = acc + o_b[c];
    }
}

// ============================================================
// Kernel 4: out_img = img + out[b,c]  (float4 streaming)
// ============================================================
__global__ void __launch_bounds__(256) k_residual(const float* __restrict__ img,
                                                  float* __restrict__ out)
{
    int idx = blockIdx.x * 256 + threadIdx.x;       // float4 index
    // total float4s = B*C*N/4 = 11,239,424 = 43904 * 256, exact
    int bc = idx / (N_ / 4);                        // N_/4 = 784
    float add = __ldg(&g_out[bc]);
    float4 x = reinterpret_cast<const float4*>(img)[idx];
    x.x += add; x.y += add; x.z += add; x.w += add;
    reinterpret_cast<float4*>(out)[idx] = x;
}

// ============================================================
extern "C" void kernel_launch(void* const* d_in, const int* in_sizes, int n_in,
                              void* d_out, int out_size)
{
    const float* text = (const float*)d_in[0];
    const float* img  = (const float*)d_in[1];
    const float* q_w  = (const float*)d_in[2];
    const float* q_b  = (const float*)d_in[3];
    const float* k_w  = (const float*)d_in[4];
    const float* k_b  = (const float*)d_in[5];
    const float* v_w  = (const float*)d_in[6];
    const float* v_b  = (const float*)d_in[7];
    const float* o_w  = (const float*)d_in[8];
    const float* o_b  = (const float*)d_in[9];
    float* out = (float*)d_out;

    k_compute_qa<<<B_, 256>>>(text, q_w, q_b, k_w, k_b);
    k_attn_pass<<<dim3(GX, B_), 256>>>(img);
    k_finish<<<B_, 256>>>(v_w, v_b, o_w, o_b);
    k_residual<<<(B_ * C_ * (N_ / 4)) / 256, 256>>>(img, out);
}

// round 4
// speedup vs baseline: 2.3495x; 1.2431x over previous
#include <cuda_runtime.h>
#include <cuda_bf16.h>
#include <cstdint>

// Problem shape (fixed by the dataset)
#define B_  32
#define T_  768
#define C_  448
#define E_  256
#define N_  3136          // H*W = 56*56
#define SCALE 0.0625f     // 1/sqrt(E)

#define CHUNK 16
#define PITCH 17              // smem row pitch (odd -> conflict-free)
#define GX 49                 // pixel-groups per batch (blocks in x)
#define CPB 4                 // chunks per block: 49*4*16 = 3136 exact

// -------- device scratch (no allocations allowed) --------
__device__ float g_q[B_ * E_];              // q = text @ q_w^T + q_b
__device__ float g_a[B_ * C_];              // scale * (q[b]^T k_w)[c]
__device__ float g_qkb[B_];                 // scale * q[b].k_b
__device__ float g_Spart[B_ * GX * C_];     // per-group weighted channel sums
__device__ float g_Dpart[B_ * GX];          // per-group exp-sum partials
__device__ float g_out[B_ * C_];            // final per-(b,c) residual add

// ============================================================
// Kernel 1a: q[b,e] = text[b] . q_w[e] + q_b[e]
// grid (8, B_): block handles 32 e; warp per 4 e.
// ============================================================
__global__ void __launch_bounds__(256) k_q(
    const float* __restrict__ text, const float* __restrict__ q_w,
    const float* __restrict__ q_b)
{
    int slice = blockIdx.x, b = blockIdx.y;
    int tid = threadIdx.x, warp = tid >> 5, lane = tid & 31;
    __shared__ float txt[T_];

    const float4* tsrc = reinterpret_cast<const float4*>(text + (size_t)b * T_);
    for (int j = tid; j < T_ / 4; j += 256)
        reinterpret_cast<float4*>(txt)[j] = tsrc[j];
    __syncthreads();

    int e0 = slice * 32 + warp * 4;
    const float4* tt = reinterpret_cast<const float4*>(txt);
    const float4* w0 = reinterpret_cast<const float4*>(q_w + (size_t)(e0 + 0) * T_);
    const float4* w1 = reinterpret_cast<const float4*>(q_w + (size_t)(e0 + 1) * T_);
    const float4* w2 = reinterpret_cast<const float4*>(q_w + (size_t)(e0 + 2) * T_);
    const float4* w3 = reinterpret_cast<const float4*>(q_w + (size_t)(e0 + 3) * T_);
    float a0 = 0.f, a1 = 0.f, a2 = 0.f, a3 = 0.f;
    #pragma unroll
    for (int it = 0; it < 6; ++it) {          // 6*32*4 = 768 exact
        int j = it * 32 + lane;
        float4 y = tt[j];
        float4 x0 = w0[j], x1 = w1[j], x2 = w2[j], x3 = w3[j];
        a0 += x0.x * y.x + x0.y * y.y + x0.z * y.z + x0.w * y.w;
        a1 += x1.x * y.x + x1.y * y.y + x1.z * y.z + x1.w * y.w;
        a2 += x2.x * y.x + x2.y * y.y + x2.z * y.z + x2.w * y.w;
        a3 += x3.x * y.x + x3.y * y.y + x3.z * y.z + x3.w * y.w;
    }
    #pragma unroll
    for (int o = 16; o > 0; o >>= 1) {
        a0 += __shfl_down_sync(0xffffffffu, a0, o);
        a1 += __shfl_down_sync(0xffffffffu, a1, o);
        a2 += __shfl_down_sync(0xffffffffu, a2, o);
        a3 += __shfl_down_sync(0xffffffffu, a3, o);
    }
    if (lane == 0) {
        g_q[b * E_ + e0 + 0] = a0 + q_b[e0 + 0];
        g_q[b * E_ + e0 + 1] = a1 + q_b[e0 + 1];
        g_q[b * E_ + e0 + 2] = a2 + q_b[e0 + 2];
        g_q[b * E_ + e0 + 3] = a3 + q_b[e0 + 3];
    }
}

// ============================================================
// Kernel 1b: a[b,c] = scale * sum_e q[e] k_w[e,c];  qkb[b].
// One block per batch; both c handled in a single fused loop.
// ============================================================
__global__ void __launch_bounds__(256) k_a(
    const float* __restrict__ k_w, const float* __restrict__ k_b)
{
    int b = blockIdx.x, tid = threadIdx.x;
    __shared__ float q_sm[E_];
    __shared__ float red[256];

    q_sm[tid] = g_q[b * E_ + tid];
    red[tid] = q_sm[tid] * k_b[tid];
    __syncthreads();
    for (int s = 128; s > 0; s >>= 1) {
        if (tid < s) red[tid] += red[tid + s];
        __syncthreads();
    }
    if (tid == 0) g_qkb[b] = SCALE * red[0];

    // fused dual-c loop: 16 loads in flight
    {
        int c0 = tid, c1 = tid + 256;       // c1 valid iff tid < 192
        float acc0 = 0.f, acc1 = 0.f;
        if (tid < 192) {
            #pragma unroll 8
            for (int e = 0; e < E_; ++e) {
                float qv = q_sm[e];
                acc0 += qv * k_w[e * C_ + c0];
                acc1 += qv * k_w[e * C_ + c1];
            }
            g_a[b * C_ + c1] = SCALE * acc1;
        } else {
            #pragma unroll 8
            for (int e = 0; e < E_; ++e) acc0 += q_sm[e] * k_w[e * C_ + c0];
        }
        g_a[b * C_ + c0] = SCALE * acc0;
    }
}

// ============================================================
// Kernel 2: attention pass with register-prefetch pipelining.
// Block (gx, b) processes CPB chunks of 16 pixels.
// ============================================================
__global__ void __launch_bounds__(256) k_attn_pass(const float* __restrict__ img)
{
    int gx = blockIdx.x, b = blockIdx.y;
    int tid = threadIdx.x;
    int warp = tid >> 5, lane = tid & 31;

    __shared__ float tile[C_ * PITCH];   // 448*17*4 = 30464 B
    __shared__ float a_sm[C_];
    __shared__ float e_sm[CHUNK];
    __shared__ float d_sm[8];

    for (int c = tid; c < C_; c += 256) a_sm[c] = g_a[b * C_ + c];
    float qkb = g_qkb[b];

    const float* base = img + (size_t)b * C_ * N_ + gx * (CPB * CHUNK);

    // precompute the 7 (c, v) pairs this thread loads/stores
    int cc[7], vv[7];
    #pragma unroll
    for (int it = 0; it < 7; ++it) {
        int idx = it * 256 + tid;           // < 1792
        cc[it] = idx >> 2; vv[it] = idx & 3;
    }

    float4 r[7];
    // prefetch chunk 0
    #pragma unroll
    for (int it = 0; it < 7; ++it)
        r[it] = *reinterpret_cast<const float4*>(base + (size_t)cc[it] * N_ + vv[it] * 4);
    // store chunk 0
    #pragma unroll
    for (int it = 0; it < 7; ++it) {
        float* t = tile + cc[it] * PITCH + vv[it] * 4;
        t[0] = r[it].x; t[1] = r[it].y; t[2] = r[it].z; t[3] = r[it].w;
    }
    __syncthreads();

    float sAcc0 = 0.f, sAcc1 = 0.f;   // channels tid and tid+256
    float dAcc = 0.f;                  // per-warp (lane0) exp-sum

    for (int i = 0; i < CPB; ++i) {
        // ---- issue prefetch of next chunk (overlaps phases A/B) ----
        if (i + 1 < CPB) {
            const float* src = base + (i + 1) * CHUNK;
            #pragma unroll
            for (int it = 0; it < 7; ++it)
                r[it] = *reinterpret_cast<const float4*>(src + (size_t)cc[it] * N_ + vv[it] * 4);
        }

        // ---- Phase A: logits. warp w owns pixels 2w, 2w+1 ----
        {
            float p0 = 0.f, p1 = 0.f;
            int px = warp * 2;
            #pragma unroll
            for (int j = 0; j < 14; ++j) {
                int c = j * 32 + lane;
                float av = a_sm[c];
                const float* t = tile + c * PITCH + px;
                p0 += av * t[0];
                p1 += av * t[1];
            }
            #pragma unroll
            for (int o = 16; o > 0; o >>= 1) {
                p0 += __shfl_xor_sync(0xffffffffu, p0, o);
                p1 += __shfl_xor_sync(0xffffffffu, p1, o);
            }
            if (lane == 0) {
                float e0 = __expf(p0 + qkb);
                float e1 = __expf(p1 + qkb);
                e_sm[px] = e0; e_sm[px + 1] = e1;
                dAcc += e0 + e1;
            }
        }
        __syncthreads();   // e_sm ready

        // ---- Phase B: S[c] += sum_j e[j] * x[c,j] ----
        {
            const float* t0 = tile + tid * PITCH;
            float a0 = 0.f, a1 = 0.f;
            if (tid < 192) {
                const float* t1 = tile + (tid + 256) * PITCH;
                #pragma unroll
                for (int j = 0; j < CHUNK; ++j) {
                    float e = e_sm[j];
                    a0 += e * t0[j];
                    a1 += e * t1[j];
                }
            } else {
                #pragma unroll
                for (int j = 0; j < CHUNK; ++j) a0 += e_sm[j] * t0[j];
            }
            sAcc0 += a0; sAcc1 += a1;
        }
        __syncthreads();   // all tile reads done

        // ---- store prefetched chunk ----
        if (i + 1 < CPB) {
            #pragma unroll
            for (int it = 0; it < 7; ++it) {
                float* t = tile + cc[it] * PITCH + vv[it] * 4;
                t[0] = r[it].x; t[1] = r[it].y; t[2] = r[it].z; t[3] = r[it].w;
            }
            __syncthreads();   // tile ready for next iteration
        }
    }

    // ---- write partials ----
    float* Sp = g_Spart + ((size_t)(b * GX + gx)) * C_;
    Sp[tid] = sAcc0;
    if (tid < 192) Sp[tid + 256] = sAcc1;

    if (lane == 0) d_sm[warp] = dAcc;
    __syncthreads();
    if (tid == 0) {
        float d = 0.f;
        #pragma unroll
        for (int w = 0; w < 8; ++w) d += d_sm[w];
        g_Dpart[b * GX + gx] = d;
    }
}

// ============================================================
// Kernel 3: reduce partials, pooled = v_w @ (s/D) + v_b,
//           out[b,c] = o_w @ pooled + o_b.  One block per batch.
// ============================================================
__global__ void __launch_bounds__(256) k_finish(
    const float* __restrict__ v_w, const float* __restrict__ v_b,
    const float* __restrict__ o_w, const float* __restrict__ o_b)
{
    int b = blockIdx.x, tid = threadIdx.x;
    int warp = tid >> 5, lane = tid & 31;
    __shared__ float s_sm[C_];
    __shared__ float pooled[E_];
    __shared__ float invD_sm;

    for (int c = tid; c < C_; c += 256) {
        const float* Sp = g_Spart + (size_t)b * GX * C_ + c;
        float a0 = 0.f;
        #pragma unroll 7
        for (int g = 0; g < GX; ++g) a0 += Sp[(size_t)g * C_];
        s_sm[c] = a0;
    }
    if (tid < 64) {
        float d = (tid < GX) ? g_Dpart[b * GX + tid] : 0.f;
        d += __shfl_xor_sync(0xffffffffu, d, 16);
        d += __shfl_xor_sync(0xffffffffu, d, 8);
        d += __shfl_xor_sync(0xffffffffu, d, 4);
        d += __shfl_xor_sync(0xffffffffu, d, 2);
        d += __shfl_xor_sync(0xffffffffu, d, 1);
        if (tid == 0) {
            float d1 = 0.f;
            for (int g = 32; g < GX; ++g) d1 += g_Dpart[b * GX + g];
            invD_sm = 1.0f / (d + d1);
        }
    }
    __syncthreads();
    float invD = invD_sm;

    // pooled[e]: warp computes pairs (16 trips), lanes coalesced over c
    for (int r = 0; r < 32; r += 2) {
        int e0 = warp * 32 + r, e1 = e0 + 1;
        const float* w0 = v_w + (size_t)e0 * C_;
        const float* w1 = v_w + (size_t)e1 * C_;
        float acc0 = 0.f, acc1 = 0.f;
        #pragma unroll
        for (int it = 0; it < 14; ++it) {
            int c = it * 32 + lane;
            float sv = s_sm[c];
            acc0 += w0[c] * sv;
            acc1 += w1[c] * sv;
        }
        #pragma unroll
        for (int o = 16; o > 0; o >>= 1) {
            acc0 += __shfl_down_sync(0xffffffffu, acc0, o);
            acc1 += __shfl_down_sync(0xffffffffu, acc1, o);
        }
        if (lane == 0) {
            pooled[e0] = acc0 * invD + v_b[e0];
            pooled[e1] = acc1 * invD + v_b[e1];
        }
    }
    __syncthreads();

    // out[b,c]: warp computes pairs (28 trips), lanes coalesced over e
    for (int r = 0; r < 56; r += 2) {
        int c0 = warp * 56 + r, c1 = c0 + 1;
        const float* w0 = o_w + (size_t)c0 * E_;
        const float* w1 = o_w + (size_t)c1 * E_;
        float acc0 = 0.f, acc1 = 0.f;
        #pragma unroll
        for (int it = 0; it < 8; ++it) {
            int e = it * 32 + lane;
            float pv = pooled[e];
            acc0 += w0[e] * pv;
            acc1 += w1[e] * pv;
        }
        #pragma unroll
        for (int o = 16; o > 0; o >>= 1) {
            acc0 += __shfl_down_sync(0xffffffffu, acc0, o);
            acc1 += __shfl_down_sync(0xffffffffu, acc1, o);
        }
        if (lane == 0) {
            g_out[b * C_ + c0] = acc0 + o_b[c0];
            g_out[b * C_ + c1] = acc1 + o_b[c1];
        }
    }
}

// ============================================================
// Kernel 4: out_img = img + out[b,c]  (float4 streaming)
// ============================================================
__global__ void __launch_bounds__(256) k_residual(const float* __restrict__ img,
                                                  float* __restrict__ out)
{
    int idx = blockIdx.x * 256 + threadIdx.x;       // float4 index
    // total float4s = B*C*N/4 = 11,239,424 = 43904 * 256, exact
    int bc = idx / (N_ / 4);                        // N_/4 = 784
    float add = __ldg(&g_out[bc]);
    float4 x = reinterpret_cast<const float4*>(img)[idx];
    x.x += add; x.y += add; x.z += add; x.w += add;
    reinterpret_cast<float4*>(out)[idx] = x;
}

// ============================================================
extern "C" void kernel_launch(void* const* d_in, const int* in_sizes, int n_in,
                              void* d_out, int out_size)
{
    const float* text = (const float*)d_in[0];
    const float* img  = (const float*)d_in[1];
    const float* q_w  = (const float*)d_in[2];
    const float* q_b  = (const float*)d_in[3];
    const float* k_w  = (const float*)d_in[4];
    const float* k_b  = (const float*)d_in[5];
    const float* v_w  = (const float*)d_in[6];
    const float* v_b  = (const float*)d_in[7];
    const float* o_w  = (const float*)d_in[8];
    const float* o_b  = (const float*)d_in[9];
    float* out = (float*)d_out;

    k_q<<<dim3(8, B_), 256>>>(text, q_w, q_b);
    k_a<<<B_, 256>>>(k_w, k_b);
    k_attn_pass<<<dim3(GX, B_), 256>>>(img);
    k_finish<<<B_, 256>>>(v_w, v_b, o_w, o_b);
    k_residual<<<(B_ * C_ * (N_ / 4)) / 256, 256>>>(img, out);
}